// round 3
// baseline (speedup 1.0000x reference)
#include <cuda_runtime.h>

#define SEQL   2048
#define BATCH  2
#define DMODEL 1024
#define NHEAD  16
#define DK     64
#define NT     (SEQL*BATCH)      // 4096 token rows
#define BH     (BATCH*NHEAD)     // 32
#define QSCALE 0.125f            // DK^-0.5

// Scratch (static device globals — no runtime allocation allowed)
__device__ float g_qT[BH*DK*SEQL];     // [bh][dk][l]  (transposed for flash)
__device__ float g_kT[BH*DK*SEQL];     // [bh][dk][s]
__device__ float g_v [BH*SEQL*DK];     // [bh][s][dk]
__device__ float g_attn[NT*DMODEL];    // merged heads [t][d]

// ---------------------------------------------------------------------------
// Generic GEMM: val[t][d] = (sum_i A[t][i] * W[d][i] + bias[d]) * scale
// 128x128 tile, 256 threads, 8x8 per-thread micro-tile (2x2 quadrants of 4x4).
// MODE 0: store head-split TRANSPOSED  [bh][dk][l]   (Q, K)
// MODE 1: store head-split natural     [bh][s][dk]   (V)
// MODE 2: store plain                  [t][d]        (final output)
// ---------------------------------------------------------------------------
template<int MODE>
__global__ void __launch_bounds__(256, 2) gemm_k(const float* __restrict__ A,
                                                 const float* __restrict__ W,
                                                 const float* __restrict__ bias,
                                                 float* __restrict__ out,
                                                 float scale)
{
    __shared__ __align__(16) float AsT[16][132];   // [k][t_local], pad->132 (528B rows, 16B aligned)
    __shared__ __align__(16) float WsT[16][132];   // [k][d_local]

    const int tid = threadIdx.x;
    const int ty = tid >> 4;      // 0..15 -> row quadrants
    const int tx = tid & 15;      // 0..15 -> col quadrants
    const int t0 = blockIdx.y * 128;
    const int d0 = blockIdx.x * 128;

    float acc[8][8];
    #pragma unroll
    for (int r = 0; r < 8; r++)
        #pragma unroll
        for (int c = 0; c < 8; c++) acc[r][c] = 0.f;

    for (int kc = 0; kc < DMODEL; kc += 16) {
        // Load + transpose 128x16 tiles of A and W into smem
        #pragma unroll
        for (int i = 0; i < 2; i++) {
            int f   = tid + i * 256;
            int row = f >> 2;            // 0..127
            int q4  = (f & 3) << 2;      // 0,4,8,12
            float4 av = *(const float4*)(A + (t0 + row) * DMODEL + kc + q4);
            AsT[q4+0][row] = av.x; AsT[q4+1][row] = av.y;
            AsT[q4+2][row] = av.z; AsT[q4+3][row] = av.w;
            float4 wv = *(const float4*)(W + (d0 + row) * DMODEL + kc + q4);
            WsT[q4+0][row] = wv.x; WsT[q4+1][row] = wv.y;
            WsT[q4+2][row] = wv.z; WsT[q4+3][row] = wv.w;
        }
        __syncthreads();

        #pragma unroll
        for (int i = 0; i < 16; i++) {
            float4 a0 = *(const float4*)&AsT[i][4*ty];
            float4 a1 = *(const float4*)&AsT[i][64 + 4*ty];
            float4 w0 = *(const float4*)&WsT[i][4*tx];
            float4 w1 = *(const float4*)&WsT[i][64 + 4*tx];
            float av[8] = {a0.x,a0.y,a0.z,a0.w,a1.x,a1.y,a1.z,a1.w};
            float wv[8] = {w0.x,w0.y,w0.z,w0.w,w1.x,w1.y,w1.z,w1.w};
            #pragma unroll
            for (int r = 0; r < 8; r++)
                #pragma unroll
                for (int c = 0; c < 8; c++)
                    acc[r][c] += av[r] * wv[c];
        }
        __syncthreads();
    }

    // Epilogue
    #pragma unroll
    for (int r = 0; r < 8; r++) {
        int t = t0 + ((r < 4) ? 4*ty + r : 60 + 4*ty + r);
        #pragma unroll
        for (int c = 0; c < 8; c++) {
            int d = d0 + ((c < 4) ? 4*tx + c : 60 + 4*tx + c);
            float val = (acc[r][c] + bias[d]) * scale;
            if (MODE == 0) {
                int l = t >> 1, b = t & 1, h = d >> 6, dk = d & 63;
                out[(((b << 4) + h) * DK + dk) * SEQL + l] = val;
            } else if (MODE == 1) {
                int l = t >> 1, b = t & 1, h = d >> 6, dk = d & 63;
                out[(((b << 4) + h) * SEQL + l) * DK + dk] = val;
            } else {
                out[t * DMODEL + d] = val;
            }
        }
    }
}

// ---------------------------------------------------------------------------
// Flash attention: one block = 128 query rows for one (b,h).
// Q/K live in smem transposed [dk][l]/[dk][s]; V natural [s][dk]; P [s][l].
// All smem compute loads are contiguous LDS.128 (conflict-free).
// ---------------------------------------------------------------------------
__global__ void __launch_bounds__(256, 1) flash_k(const float* __restrict__ qT,
                                                  const float* __restrict__ kT,
                                                  const float* __restrict__ v,
                                                  float* __restrict__ outm)
{
    extern __shared__ float sm[];
    float* QsT = sm;                    // [64][132]  (dk, l_local)
    float* KsT = sm + 64*132;           // [64][132]  (dk, s_local)
    float* Vs  = KsT + 64*132;          // [128][68]  (s_local, dk)
    float* Ps  = Vs + 128*68;           // [128][132] (s_local, l_local)

    const int tid = threadIdx.x;
    const int ty = tid >> 4;
    const int tx = tid & 15;
    const int bh = blockIdx.y;
    const int l0 = blockIdx.x * 128;

    const float* qb = qT + bh * DK * SEQL;
    const float* kb = kT + bh * DK * SEQL;
    const float* vb = v  + bh * SEQL * DK;

    // Load Q tile once: 64 dk-rows x 128 l
    #pragma unroll
    for (int i = 0; i < 8; i++) {
        int f  = tid + i * 256;
        int dk = f >> 5;
        int l4 = (f & 31) << 2;
        *(float4*)&QsT[dk*132 + l4] = *(const float4*)(qb + dk*SEQL + l0 + l4);
    }

    float o[8][4];
    float mrow[8], lrow[8];
    #pragma unroll
    for (int r = 0; r < 8; r++) {
        mrow[r] = -1e30f; lrow[r] = 0.f;
        #pragma unroll
        for (int c = 0; c < 4; c++) o[r][c] = 0.f;
    }

    for (int s0 = 0; s0 < SEQL; s0 += 128) {
        // Load K chunk (transposed layout in global already) and V chunk
        #pragma unroll
        for (int i = 0; i < 8; i++) {
            int f  = tid + i * 256;
            int dk = f >> 5;
            int s4 = (f & 31) << 2;
            *(float4*)&KsT[dk*132 + s4] = *(const float4*)(kb + dk*SEQL + s0 + s4);
        }
        #pragma unroll
        for (int i = 0; i < 8; i++) {
            int f  = tid + i * 256;
            int sl = f >> 4;
            int d4 = (f & 15) << 2;
            *(float4*)&Vs[sl*68 + d4] = *(const float4*)(vb + (s0 + sl)*DK + d4);
        }
        __syncthreads();

        // Scores: 128x128 tile, contract over dk=64
        float sacc[8][8];
        #pragma unroll
        for (int r = 0; r < 8; r++)
            #pragma unroll
            for (int c = 0; c < 8; c++) sacc[r][c] = 0.f;

        #pragma unroll 4
        for (int kk = 0; kk < 64; kk++) {
            float4 q0 = *(const float4*)&QsT[kk*132 + 4*ty];
            float4 q1 = *(const float4*)&QsT[kk*132 + 64 + 4*ty];
            float4 k0 = *(const float4*)&KsT[kk*132 + 4*tx];
            float4 k1 = *(const float4*)&KsT[kk*132 + 64 + 4*tx];
            float qv[8] = {q0.x,q0.y,q0.z,q0.w,q1.x,q1.y,q1.z,q1.w};
            float kv[8] = {k0.x,k0.y,k0.z,k0.w,k1.x,k1.y,k1.z,k1.w};
            #pragma unroll
            for (int r = 0; r < 8; r++)
                #pragma unroll
                for (int c = 0; c < 8; c++)
                    sacc[r][c] += qv[r] * kv[c];
        }

        // Online softmax (rows shared by the 16 lanes of each half-warp)
        #pragma unroll
        for (int r = 0; r < 8; r++) {
            float mx = sacc[r][0];
            #pragma unroll
            for (int c = 1; c < 8; c++) mx = fmaxf(mx, sacc[r][c]);
            mx = fmaxf(mx, __shfl_xor_sync(0xffffffffu, mx, 1));
            mx = fmaxf(mx, __shfl_xor_sync(0xffffffffu, mx, 2));
            mx = fmaxf(mx, __shfl_xor_sync(0xffffffffu, mx, 4));
            mx = fmaxf(mx, __shfl_xor_sync(0xffffffffu, mx, 8));
            float mn = fmaxf(mrow[r], mx);
            float a  = __expf(mrow[r] - mn);
            mrow[r] = mn;
            float ls = 0.f;
            #pragma unroll
            for (int c = 0; c < 8; c++) {
                float p = __expf(sacc[r][c] - mn);
                sacc[r][c] = p;
                ls += p;
            }
            ls += __shfl_xor_sync(0xffffffffu, ls, 1);
            ls += __shfl_xor_sync(0xffffffffu, ls, 2);
            ls += __shfl_xor_sync(0xffffffffu, ls, 4);
            ls += __shfl_xor_sync(0xffffffffu, ls, 8);
            lrow[r] = lrow[r] * a + ls;
            #pragma unroll
            for (int c = 0; c < 4; c++) o[r][c] *= a;
        }

        // Stage P transposed: Ps[s_local][l_local]
        #pragma unroll
        for (int c = 0; c < 8; c++) {
            int sc = (c < 4) ? 4*tx + c : 60 + 4*tx + c;
            #pragma unroll
            for (int r = 0; r < 8; r++) {
                int lr = (r < 4) ? 4*ty + r : 60 + 4*ty + r;
                Ps[sc*132 + lr] = sacc[r][c];
            }
        }
        __syncthreads();

        // O += P @ V  (contract over s=128), O is 128 x 64
        #pragma unroll 4
        for (int s = 0; s < 128; s++) {
            float4 p0 = *(const float4*)&Ps[s*132 + 4*ty];
            float4 p1 = *(const float4*)&Ps[s*132 + 64 + 4*ty];
            float4 vv = *(const float4*)&Vs[s*68 + 4*tx];
            float pv[8] = {p0.x,p0.y,p0.z,p0.w,p1.x,p1.y,p1.z,p1.w};
            float vr[4] = {vv.x,vv.y,vv.z,vv.w};
            #pragma unroll
            for (int r = 0; r < 8; r++)
                #pragma unroll
                for (int c = 0; c < 4; c++)
                    o[r][c] += pv[r] * vr[c];
        }
        __syncthreads();   // protect KsT/Vs/Ps before next chunk overwrites
    }

    // Write merged-head layout: attn[(l*B + b)*D + h*64 + dk]
    const int b = bh >> 4, h = bh & 15;
    #pragma unroll
    for (int r = 0; r < 8; r++) {
        int l = l0 + ((r < 4) ? 4*ty + r : 60 + 4*ty + r);
        float inv = 1.f / lrow[r];
        float4 ov = make_float4(o[r][0]*inv, o[r][1]*inv, o[r][2]*inv, o[r][3]*inv);
        *(float4*)(outm + (l * BATCH + b) * DMODEL + h * DK + 4*tx) = ov;
    }
}

// ---------------------------------------------------------------------------
extern "C" void kernel_launch(void* const* d_in, const int* in_sizes, int n_in,
                              void* d_out, int out_size)
{
    const float* query = (const float*)d_in[0];
    const float* key   = (const float*)d_in[1];
    const float* value = (const float*)d_in[2];
    const float* WQ  = (const float*)d_in[3];
    const float* WQb = (const float*)d_in[4];
    const float* WK  = (const float*)d_in[5];
    const float* WKb = (const float*)d_in[6];
    const float* WV  = (const float*)d_in[7];
    const float* WVb = (const float*)d_in[8];
    const float* WO  = (const float*)d_in[9];
    const float* WOb = (const float*)d_in[10];
    float* out = (float*)d_out;

    float *qT, *kT, *vN, *attn;
    cudaGetSymbolAddress((void**)&qT,   g_qT);
    cudaGetSymbolAddress((void**)&kT,   g_kT);
    cudaGetSymbolAddress((void**)&vN,   g_v);
    cudaGetSymbolAddress((void**)&attn, g_attn);

    const int flash_smem = (64*132 + 64*132 + 128*68 + 128*132) * 4;  // 169984 B
    cudaFuncSetAttribute(flash_k, cudaFuncAttributeMaxDynamicSharedMemorySize, flash_smem);

    dim3 gblk(256);
    dim3 ggrid(DMODEL/128, NT/128);   // (8, 32)

    gemm_k<0><<<ggrid, gblk>>>(query, WQ, WQb, qT, QSCALE);  // Q (scaled)
    gemm_k<0><<<ggrid, gblk>>>(key,   WK, WKb, kT, 1.0f);    // K
    gemm_k<1><<<ggrid, gblk>>>(value, WV, WVb, vN, 1.0f);    // V

    flash_k<<<dim3(SEQL/128, BH), 256, flash_smem>>>(qT, kT, vN, attn);

    gemm_k<2><<<ggrid, gblk>>>(attn, WO, WOb, out, 1.0f);    // output proj
}